// round 7
// baseline (speedup 1.0000x reference)
#include <cuda_runtime.h>
#include <cstdint>

#define S_LEN 512
#define B_SZ  64
#define HIDD  1024
#define EMBD  512
#define NCLS  32000
#define FEATD 2048
#define RNN_NCTA 128
// hshf [128k][64b] float = 32KB ; Wd dup [128k][128] float = 64KB
#define RNN_SMEM (128 * 64 * 4 + 128 * 128 * 4)

#define FFMA2(d, a, b) asm("fma.rn.f32x2 %0, %1, %2, %0;" : "+l"(d) : "l"(a), "l"(b))
#define REDGF(p, v) asm volatile("red.global.add.f32 [%0], %1;" :: "l"(p), "f"(v) : "memory")
union F2U { unsigned long long u; float2 f; };

// ---- device scratch ----
__device__ float g_G[(size_t)S_LEN * B_SZ * HIDD];     // seeded with G, accumulated to preact
__device__ float g_OUT[(size_t)S_LEN * B_SZ * HIDD];   // h_t (for attention)
__device__ float g_scores[(S_LEN - 1) * B_SZ];
__device__ float g_attn[(S_LEN - 1) * B_SZ];
__device__ float g_attout[B_SZ * HIDD];
__device__ unsigned g_bar_grp[8 * 32];   // 8 counters on distinct 128B lines
__device__ unsigned g_bar_root;
__device__ volatile unsigned g_bar_gen;

__global__ void init_kernel() {
    int i = blockIdx.x * blockDim.x + threadIdx.x;
    if (i < 8 * 32) g_bar_grp[i] = 0u;
    if (i == 0) { g_bar_root = 0u; *(unsigned*)&g_bar_gen = 0u; }
}

// ---- K1: gates  G[(t*64+b)][j] = emb[X[b,t]] . W_ih[j] + b_ih[j] + b_hh[j] ----
__global__ void __launch_bounds__(256) gates_kernel(const int* __restrict__ X,
                                                    const float* __restrict__ emb,
                                                    const float* __restrict__ W_ih,
                                                    const float* __restrict__ b_ih,
                                                    const float* __restrict__ b_hh) {
    __shared__ float2 As2[16 * 64];
    __shared__ float  Bs[16 * 68];
    __shared__ int rowidx[64];
    const int n0 = blockIdx.x * 64;
    const int m0 = blockIdx.y * 64;
    const int tid = threadIdx.x;

    if (tid < 64) {
        int m = m0 + tid;
        int t = m >> 6, b = m & 63;
        rowidx[tid] = X[b * S_LEN + t];
    }
    __syncthreads();

    const int tx = tid & 15, ty = tid >> 4;
    unsigned long long acc[4][2];
#pragma unroll
    for (int i = 0; i < 4; i++) { acc[i][0] = 0ull; acc[i][1] = 0ull; }

    const int lm = tid >> 2;
    const int lk = (tid & 3) * 4;

    for (int k0 = 0; k0 < EMBD; k0 += 16) {
        float4 av = *(const float4*)&emb[(size_t)rowidx[lm] * EMBD + k0 + lk];
        As2[(lk + 0) * 64 + lm] = make_float2(av.x, av.x);
        As2[(lk + 1) * 64 + lm] = make_float2(av.y, av.y);
        As2[(lk + 2) * 64 + lm] = make_float2(av.z, av.z);
        As2[(lk + 3) * 64 + lm] = make_float2(av.w, av.w);
        float4 bv = *(const float4*)&W_ih[(size_t)(n0 + lm) * EMBD + k0 + lk];
        Bs[(lk + 0) * 68 + lm] = bv.x; Bs[(lk + 1) * 68 + lm] = bv.y;
        Bs[(lk + 2) * 68 + lm] = bv.z; Bs[(lk + 3) * 68 + lm] = bv.w;
        __syncthreads();
#pragma unroll
        for (int kk = 0; kk < 16; kk++) {
            ulonglong2 a01 = *(const ulonglong2*)&As2[kk * 64 + ty * 4];
            ulonglong2 a23 = *(const ulonglong2*)&As2[kk * 64 + ty * 4 + 2];
            ulonglong2 bp  = *(const ulonglong2*)&Bs[kk * 68 + tx * 4];
            FFMA2(acc[0][0], a01.x, bp.x); FFMA2(acc[0][1], a01.x, bp.y);
            FFMA2(acc[1][0], a01.y, bp.x); FFMA2(acc[1][1], a01.y, bp.y);
            FFMA2(acc[2][0], a23.x, bp.x); FFMA2(acc[2][1], a23.x, bp.y);
            FFMA2(acc[3][0], a23.y, bp.x); FFMA2(acc[3][1], a23.y, bp.y);
        }
        __syncthreads();
    }
    float4 bi = *(const float4*)&b_ih[n0 + tx * 4];
    float4 bh = *(const float4*)&b_hh[n0 + tx * 4];
    float bias[4] = {bi.x + bh.x, bi.y + bh.y, bi.z + bh.z, bi.w + bh.w};
#pragma unroll
    for (int i = 0; i < 4; i++) {
        int m = m0 + ty * 4 + i;
        F2U p0, p1; p0.u = acc[i][0]; p1.u = acc[i][1];
        float4 o = make_float4(p0.f.x + bias[0], p0.f.y + bias[1],
                               p1.f.x + bias[2], p1.f.y + bias[3]);
        *(float4*)&g_G[(size_t)m * HIDD + n0 + tx * 4] = o;
    }
}

// ---- tree grid barrier: 8 parallel arrive lines + root ----
__device__ __forceinline__ void grid_bar(unsigned target, int cta) {
    __threadfence();
    __syncthreads();
    if (threadIdx.x == 0) {
        unsigned grp = (unsigned)(cta & 7);
        unsigned a = atomicAdd(&g_bar_grp[grp * 32], 1u);
        if (a == 15u) {
            unsigned r = atomicAdd(&g_bar_root, 1u);
            if (r == 7u) {
                g_bar_root = 0u;
#pragma unroll
                for (int g = 0; g < 8; g++) g_bar_grp[g * 32] = 0u;
                __threadfence();
                atomicAdd((unsigned*)&g_bar_gen, 1u);
            }
        }
        while (*(volatile unsigned*)&g_bar_gen < target) __nanosleep(16);
        __threadfence();
    }
    __syncthreads();
}

// ---- K2: persistent recurrence — K-split 8, REDG into g_G, ONE barrier/step ----
// CTA c: jg = c & 15 (64 j-cols), ks = c >> 4 (128 k each). 256 threads.
__global__ void __launch_bounds__(256, 1) rnn_kernel(const float* __restrict__ W_hh) {
    extern __shared__ char smem_raw[];
    float* hshf = (float*)smem_raw;                    // [128k][64b]
    float* Wd   = (float*)(smem_raw + 128 * 64 * 4);   // [128k][128] dup: Wd[k][2j]=(w,w)
    const int tid = threadIdx.x;
    const int c = blockIdx.x;
    const int jg = c & 15;
    const int ks = c >> 4;

    // resident W slice, k-major, duplicated
    {
        int jl = tid & 63;
        int kc = (tid >> 6) * 32;
        const float* wr = &W_hh[(size_t)(jg * 64 + jl) * HIDD + ks * 128 + kc];
#pragma unroll
        for (int q = 0; q < 8; q++) {
            float4 wv = *(const float4*)&wr[q * 4];
            *(float2*)&Wd[(kc + q * 4 + 0) * 128 + 2 * jl] = make_float2(wv.x, wv.x);
            *(float2*)&Wd[(kc + q * 4 + 1) * 128 + 2 * jl] = make_float2(wv.y, wv.y);
            *(float2*)&Wd[(kc + q * 4 + 2) * 128 + 2 * jl] = make_float2(wv.z, wv.z);
            *(float2*)&Wd[(kc + q * 4 + 3) * 128 + 2 * jl] = make_float2(wv.w, wv.w);
        }
    }
    __syncthreads();

    const int b0  = (tid & 7) * 8;    // 8 b's per thread
    const int jl0 = (tid >> 3) * 2;   // 2 j's per thread (local, 0..62)
    const int sb  = tid & 63;         // staging batch
    const int skc = (tid >> 6) * 32;  // staging k-chunk (32 k's)

    for (int t = 0; t < S_LEN; ++t) {
        // ---- stage h(t-1) = tanh(g_G[t-1]) into SMEM; 1/16 write-through to g_OUT ----
        if (t == 0) {
#pragma unroll
            for (int q = 0; q < 32; q++) hshf[(skc + q) * 64 + sb] = 0.f;
        } else {
            const size_t rowbase = (size_t)(t - 1) * B_SZ * HIDD + (size_t)sb * HIDD + ks * 128 + skc;
            const bool wout = (jg == (sb & 15));
#pragma unroll
            for (int q = 0; q < 8; q++) {
                float4 gv = __ldcg((const float4*)&g_G[rowbase + q * 4]);
                float4 hv = make_float4(tanhf(gv.x), tanhf(gv.y), tanhf(gv.z), tanhf(gv.w));
                hshf[(skc + q * 4 + 0) * 64 + sb] = hv.x;
                hshf[(skc + q * 4 + 1) * 64 + sb] = hv.y;
                hshf[(skc + q * 4 + 2) * 64 + sb] = hv.z;
                hshf[(skc + q * 4 + 3) * 64 + sb] = hv.w;
                if (wout) __stcg((float4*)&g_OUT[rowbase + q * 4], hv);
            }
        }
        __syncthreads();

        // ---- compute partials: tile 8b x 2j ----
        unsigned long long acc[2][4];   // acc[j][bpair]
#pragma unroll
        for (int i = 0; i < 2; i++)
#pragma unroll
            for (int p = 0; p < 4; p++) acc[i][p] = 0ull;

#pragma unroll 8
        for (int kk = 0; kk < 128; kk++) {
            ulonglong2 hA = *(const ulonglong2*)&hshf[kk * 64 + b0];      // (b0,b1),(b2,b3)
            ulonglong2 hB = *(const ulonglong2*)&hshf[kk * 64 + b0 + 4];  // (b4,b5),(b6,b7)
            ulonglong2 wp = *(const ulonglong2*)&Wd[kk * 128 + 2 * jl0];  // dup(j0), dup(j1)
            FFMA2(acc[0][0], hA.x, wp.x); FFMA2(acc[0][1], hA.y, wp.x);
            FFMA2(acc[0][2], hB.x, wp.x); FFMA2(acc[0][3], hB.y, wp.x);
            FFMA2(acc[1][0], hA.x, wp.y); FFMA2(acc[1][1], hA.y, wp.y);
            FFMA2(acc[1][2], hB.x, wp.y); FFMA2(acc[1][3], hB.y, wp.y);
        }

        // ---- REDG partials onto g_G[t] (pre-seeded with G) ----
        {
            float* gt = &g_G[(size_t)t * B_SZ * HIDD];
#pragma unroll
            for (int p = 0; p < 4; p++) {
                F2U a0, a1; a0.u = acc[0][p]; a1.u = acc[1][p];
                float* r0 = gt + (size_t)(b0 + 2 * p) * HIDD + jg * 64 + jl0;
                float* r1 = gt + (size_t)(b0 + 2 * p + 1) * HIDD + jg * 64 + jl0;
                REDGF(r0, a0.f.x); REDGF(r0 + 1, a1.f.x);
                REDGF(r1, a0.f.y); REDGF(r1 + 1, a1.f.y);
            }
        }
        grid_bar((unsigned)(t + 1), c);   // all partials of step t visible
    }

    // ---- epilogue: write last state h(S-1) to g_OUT ----
    {
        const size_t rowbase = (size_t)(S_LEN - 1) * B_SZ * HIDD + (size_t)sb * HIDD + ks * 128 + skc;
        if (jg == (sb & 15)) {
#pragma unroll
            for (int q = 0; q < 8; q++) {
                float4 gv = __ldcg((const float4*)&g_G[rowbase + q * 4]);
                float4 hv = make_float4(tanhf(gv.x), tanhf(gv.y), tanhf(gv.z), tanhf(gv.w));
                __stcg((float4*)&g_OUT[rowbase + q * 4], hv);
            }
        }
    }
}

// ---- K3a: scores ----
__global__ void __launch_bounds__(256) scores_kernel() {
    const int s = blockIdx.x;
    const int w = threadIdx.x >> 5, lane = threadIdx.x & 31;
    const float* Pv = g_OUT + (size_t)s * B_SZ * HIDD;
    const float* Lv = g_OUT + (size_t)(S_LEN - 1) * B_SZ * HIDD;
#pragma unroll
    for (int i = 0; i < 8; i++) {
        int b = w * 8 + i;
        const float* p = Pv + (size_t)b * HIDD;
        const float* l = Lv + (size_t)b * HIDD;
        float acc = 0.f;
#pragma unroll 4
        for (int k = lane; k < HIDD; k += 32) acc += p[k] * l[k];
#pragma unroll
        for (int o = 16; o > 0; o >>= 1) acc += __shfl_down_sync(0xffffffffu, acc, o);
        if (lane == 0) g_scores[s * B_SZ + b] = acc;
    }
}

// ---- K3b: softmax over s per b ----
__global__ void __launch_bounds__(512) softmax_kernel() {
    const int b = blockIdx.x;
    const int tid = threadIdx.x;
    __shared__ float red[512];
    float v = (tid < S_LEN - 1) ? g_scores[tid * B_SZ + b] : -1e30f;
    red[tid] = v;
    __syncthreads();
    for (int s = 256; s > 0; s >>= 1) {
        if (tid < s) red[tid] = fmaxf(red[tid], red[tid + s]);
        __syncthreads();
    }
    float m = red[0];
    __syncthreads();
    float e = (tid < S_LEN - 1) ? expf(v - m) : 0.f;
    red[tid] = e;
    __syncthreads();
    for (int s = 256; s > 0; s >>= 1) {
        if (tid < s) red[tid] += red[tid + s];
        __syncthreads();
    }
    float inv = 1.f / red[0];
    if (tid < S_LEN - 1) g_attn[tid * B_SZ + b] = e * inv;
}

// ---- K3c: att_out ----
__global__ void __launch_bounds__(256) attout_kernel() {
    const int b = blockIdx.y;
    const int h = blockIdx.x * 256 + threadIdx.x;
    float acc = 0.f;
#pragma unroll 4
    for (int s = 0; s < S_LEN - 1; s++)
        acc += g_attn[s * B_SZ + b] * g_OUT[(size_t)s * B_SZ * HIDD + (size_t)b * HIDD + h];
    g_attout[b * HIDD + h] = acc;
}

// ---- K4: out GEMM ----
__global__ void __launch_bounds__(256) out_gemm_kernel(const float* __restrict__ W_out,
                                                       const float* __restrict__ b_out,
                                                       float* __restrict__ out) {
    __shared__ float2 Fs2[16 * 64];
    __shared__ float  Ws[16 * 132];
    const int n0 = blockIdx.x * 128;
    const int tid = threadIdx.x;
    const int tx = tid & 31, ty = tid >> 5;
    const float* last = g_OUT + (size_t)(S_LEN - 1) * B_SZ * HIDD;

    unsigned long long acc[8][2];
#pragma unroll
    for (int i = 0; i < 8; i++) { acc[i][0] = 0ull; acc[i][1] = 0ull; }

    const int mm = tid >> 2;
    const int kq = (tid & 3) * 4;

    for (int k0 = 0; k0 < FEATD; k0 += 16) {
        int k = k0 + kq;
        const float* src = (k < HIDD) ? &g_attout[mm * HIDD + k]
                                      : &last[(size_t)mm * HIDD + (k - HIDD)];
        float4 fv = *(const float4*)src;
        Fs2[(kq + 0) * 64 + mm] = make_float2(fv.x, fv.x);
        Fs2[(kq + 1) * 64 + mm] = make_float2(fv.y, fv.y);
        Fs2[(kq + 2) * 64 + mm] = make_float2(fv.z, fv.z);
        Fs2[(kq + 3) * 64 + mm] = make_float2(fv.w, fv.w);
#pragma unroll
        for (int r = 0; r < 2; r++) {
            int f = tid + r * 256;
            int nn = f >> 2;
            int kq2 = (f & 3) * 4;
            float4 wv = *(const float4*)&W_out[(size_t)(n0 + nn) * FEATD + k0 + kq2];
            Ws[(kq2 + 0) * 132 + nn] = wv.x; Ws[(kq2 + 1) * 132 + nn] = wv.y;
            Ws[(kq2 + 2) * 132 + nn] = wv.z; Ws[(kq2 + 3) * 132 + nn] = wv.w;
        }
        __syncthreads();
#pragma unroll
        for (int kk = 0; kk < 16; kk++) {
            ulonglong2 a01 = *(const ulonglong2*)&Fs2[kk * 64 + ty * 8];
            ulonglong2 a23 = *(const ulonglong2*)&Fs2[kk * 64 + ty * 8 + 2];
            ulonglong2 a45 = *(const ulonglong2*)&Fs2[kk * 64 + ty * 8 + 4];
            ulonglong2 a67 = *(const ulonglong2*)&Fs2[kk * 64 + ty * 8 + 6];
            ulonglong2 wp  = *(const ulonglong2*)&Ws[kk * 132 + tx * 4];
            FFMA2(acc[0][0], a01.x, wp.x); FFMA2(acc[0][1], a01.x, wp.y);
            FFMA2(acc[1][0], a01.y, wp.x); FFMA2(acc[1][1], a01.y, wp.y);
            FFMA2(acc[2][0], a23.x, wp.x); FFMA2(acc[2][1], a23.x, wp.y);
            FFMA2(acc[3][0], a23.y, wp.x); FFMA2(acc[3][1], a23.y, wp.y);
            FFMA2(acc[4][0], a45.x, wp.x); FFMA2(acc[4][1], a45.x, wp.y);
            FFMA2(acc[5][0], a45.y, wp.x); FFMA2(acc[5][1], a45.y, wp.y);
            FFMA2(acc[6][0], a67.x, wp.x); FFMA2(acc[6][1], a67.x, wp.y);
            FFMA2(acc[7][0], a67.y, wp.x); FFMA2(acc[7][1], a67.y, wp.y);
        }
        __syncthreads();
    }
    float4 bo = *(const float4*)&b_out[n0 + tx * 4];
#pragma unroll
    for (int i = 0; i < 8; i++) {
        int m = ty * 8 + i;
        F2U p0, p1; p0.u = acc[i][0]; p1.u = acc[i][1];
        float4 o = make_float4(p0.f.x + bo.x, p0.f.y + bo.y,
                               p1.f.x + bo.z, p1.f.y + bo.w);
        *(float4*)&out[(size_t)m * NCLS + n0 + tx * 4] = o;
    }
}

// ---- launch ----
extern "C" void kernel_launch(void* const* d_in, const int* in_sizes, int n_in,
                              void* d_out, int out_size) {
    (void)in_sizes; (void)n_in; (void)out_size;
    const int*   X     = (const int*)d_in[0];
    const float* emb   = (const float*)d_in[1];
    const float* W_ih  = (const float*)d_in[2];
    const float* W_hh  = (const float*)d_in[3];
    const float* b_ih  = (const float*)d_in[4];
    const float* b_hh  = (const float*)d_in[5];
    const float* W_out = (const float*)d_in[6];
    const float* b_out = (const float*)d_in[7];
    float* out = (float*)d_out;

    static bool attr_set = false;
    if (!attr_set) {
        cudaFuncSetAttribute(rnn_kernel, cudaFuncAttributeMaxDynamicSharedMemorySize, RNN_SMEM);
        attr_set = true;
    }

    init_kernel<<<1, 256>>>();
    gates_kernel<<<dim3(HIDD / 64, (S_LEN * B_SZ) / 64), 256>>>(X, emb, W_ih, b_ih, b_hh);
    rnn_kernel<<<RNN_NCTA, 256, RNN_SMEM>>>(W_hh);
    scores_kernel<<<S_LEN - 1, 256>>>();
    softmax_kernel<<<B_SZ, 512>>>();
    attout_kernel<<<dim3(HIDD / 256, B_SZ), 256>>>();
    out_gemm_kernel<<<NCLS / 128, 256>>>(W_out, b_out, out);
}